// round 9
// baseline (speedup 1.0000x reference)
#include <cuda_runtime.h>

#define TT 256
#define MM 16
#define HH 256
#define II 128
#define NROW (MM*HH)          // 4096
#define NB 128                // 128 CTAs * 32 warps = 4096 rows
#define NTHR 1024
#define BIN_THR 256
#define KMAX 6                // wm slices cached in SMEM per row
#define SLOT (KMAX+1)         // +1 slot for wrec
#define WS_FLOATS (32*SLOT*HH)          // 224 KB
#define DSMEM_BYTES (WS_FLOATS*4)

#define DT_ 0.042f
#define GAMMA_ 2.7f
#define EPS_ 4.7f

// ---- persistent scratch (no cudaMalloc allowed) ----
__device__ float    g_B[TT*NROW];     // W_in@u + bias, 4 MB
__device__ float    g_hy[2][NROW];    // double-buffered published hy
__device__ unsigned g_bar;

// ============================================================
// Precompute B[t, m*H+h]
// ============================================================
__global__ void bin_kernel(const float* __restrict__ x,
                           const float* __restrict__ input_mask,
                           const float* __restrict__ W_in,
                           const float* __restrict__ bias) {
    __shared__ float4 xs[II/4];
    int t = blockIdx.x, m = blockIdx.y, h = threadIdx.x;
    if (h < II/4) xs[h] = ((const float4*)(x + (size_t)t*II))[h];
    __syncthreads();
    const float4* w4 = (const float4*)(W_in + ((size_t)m*HH + h)*II);
    float s = 0.f;
#pragma unroll
    for (int k = 0; k < II/4; ++k) {
        float4 a = w4[k], b = xs[k];
        s += a.x*b.x + a.y*b.y + a.z*b.z + a.w*b.w;
    }
    g_B[((size_t)t*MM + m)*HH + h] = input_mask[m]*s + bias[m*HH + h];
}

__device__ __forceinline__ float dotf4(float4 a, float4 b) {
    return a.x*b.x + a.y*b.y + a.z*b.z + a.w*b.w;
}

// ============================================================
// Persistent step kernel. One warp owns one row forever.
// row = wid*128 + blockIdx.x (every CTA holds 2 rows of each module
// -> balanced). Weights: KMAX slices + wrec in SMEM, rest from L2.
// hy: read straight from L2 (no smem snapshot phase).
// ============================================================
__global__ void __launch_bounds__(NTHR, 1)
step_kernel(const float* __restrict__ wm,
            const float* __restrict__ conn,
            const float* __restrict__ wrec,
            float* __restrict__ out) {
    extern __shared__ float4 ws4[];      // [32][SLOT][64] float4 = 224 KB
    __shared__ int   list_sh[MM][MM];
    __shared__ int   cnt_sh[MM];
    __shared__ float scal_sh[MM];

    int tid  = threadIdx.x;
    int lane = tid & 31;
    int wid  = tid >> 5;
    int row  = wid * 128 + blockIdx.x;   // balanced mapping, fixed forever
    int i = row >> 8, h = row & (HH-1);
    int wsbase = wid * SLOT * 64;

    if (tid < MM) {
        int c = 0; float s = 0.f;
#pragma unroll
        for (int o = 0; o < MM; ++o) {
            float v = conn[tid*MM + o];
            s += v;
            if (v != 0.f) list_sh[tid][c++] = o;
        }
        cnt_sh[tid]  = c;
        scal_sh[tid] = 1.f / fmaxf(s, 1.f);
    }
    __syncthreads();

    const int   cnt  = cnt_sh[i];
    const int   KC   = cnt < KMAX ? cnt : KMAX;
    const float scal = scal_sh[i];
    const float*  wmbase = wm + ((size_t)i*MM*HH + h)*HH;
    const float4* wr4    = (const float4*)(wrec + ((size_t)i*HH + h)*HH);

    // ---- one-time weight preload into SMEM ----
    for (int k = 0; k < KC; ++k) {
        int o = list_sh[i][k];
        const float4* src = (const float4*)(wmbase + (size_t)o*HH*HH);
        ws4[wsbase + k*64 + lane]      = src[lane];
        ws4[wsbase + k*64 + 32 + lane] = src[lane + 32];
    }
    ws4[wsbase + KMAX*64 + lane]      = wr4[lane];
    ws4[wsbase + KMAX*64 + 32 + lane] = wr4[lane + 32];

    float hyp = 0.f, hzp = 0.f;
    float Bv  = g_B[row];                 // t=0 prefetch

    float* state_out = out;                       // [T][M][2][H]
    float* fb_out    = out + (size_t)TT*MM*2*HH;  // [T][M][H]

    unsigned* barp = &g_bar;

    for (int t = 0; t < TT; ++t) {
        int p = t & 1;
        const float4* hy4 = (const float4*)g_hy[p];

        float fb0 = 0.f, fb1 = 0.f;

        // ---- cached blocks: weights from SMEM, hy from L2 ----
        for (int kk = 0; kk < KC; ++kk) {
            int o = list_sh[i][kk];
            float4 b0 = __ldcg(hy4 + o*64 + lane);
            float4 b1 = __ldcg(hy4 + o*64 + 32 + lane);
            float4 a0 = ws4[wsbase + kk*64 + lane];
            float4 a1 = ws4[wsbase + kk*64 + 32 + lane];
            fb0 += dotf4(a0, b0) + dotf4(a1, b1);
        }
        // ---- uncached blocks: weights + hy from L2 ----
        for (int k = KC; k < cnt; ++k) {
            int o = list_sh[i][k];
            const float4* w0 = (const float4*)(wmbase + (size_t)o*HH*HH);
            float4 b0 = __ldcg(hy4 + o*64 + lane);
            float4 b1 = __ldcg(hy4 + o*64 + 32 + lane);
            float4 a0 = w0[lane], a1 = w0[lane+32];
            fb1 += dotf4(a0, b0) + dotf4(a1, b1);
        }
        // ---- wrec from SMEM ----
        float rec;
        {
            float4 b0 = __ldcg(hy4 + i*64 + lane);
            float4 b1 = __ldcg(hy4 + i*64 + 32 + lane);
            float4 a0 = ws4[wsbase + KMAX*64 + lane];
            float4 a1 = ws4[wsbase + KMAX*64 + 32 + lane];
            rec = dotf4(a0, b0) + dotf4(a1, b1);
        }

        float fb = fb0 + fb1;
#pragma unroll
        for (int off = 16; off; off >>= 1) {
            fb  += __shfl_xor_sync(0xffffffffu, fb,  off);
            rec += __shfl_xor_sync(0xffffffffu, rec, off);
        }
        fb *= scal;
        float pre = fb + rec + Bv;
        float hzn = hzp + DT_ * (tanhf(pre) - GAMMA_*hyp - EPS_*hzp);
        float hyn = hyp + DT_ * hzn;
        hzp = hzn; hyp = hyn;

        if (lane == 0) {
            size_t sb = ((size_t)(t*MM + i)*2)*HH;
            state_out[sb + h]      = hyn;
            state_out[sb + HH + h] = hzn;
            fb_out[(size_t)(t*MM + i)*HH + h] = fb;
            __stcg(&g_hy[1-p][row], hyn);    // publish for next step
        }

        if (t == TT-1) break;

        // prefetch next-step B while the barrier drains
        Bv = g_B[(size_t)(t+1)*NROW + row];

        __syncthreads();                     // all rows of CTA published
        if (tid == 0) {
            asm volatile("red.release.gpu.global.add.u32 [%0], 1;"
                         :: "l"(barp) : "memory");
            unsigned target = (unsigned)NB * (unsigned)(t + 1);
            unsigned v;
            do {
                asm volatile("ld.acquire.gpu.global.u32 %0, [%1];"
                             : "=r"(v) : "l"(barp) : "memory");
            } while (v < target);
        }
        __syncthreads();
    }
}

extern "C" void kernel_launch(void* const* d_in, const int* in_sizes, int n_in,
                              void* d_out, int out_size) {
    const float* x     = (const float*)d_in[0];
    const float* wm    = (const float*)d_in[1];
    const float* conn  = (const float*)d_in[2];
    const float* mask  = (const float*)d_in[3];
    const float* W_in  = (const float*)d_in[4];
    const float* W_rec = (const float*)d_in[5];
    const float* bias  = (const float*)d_in[6];
    float* out = (float*)d_out;

    void *hy_ptr, *bar_ptr;
    cudaGetSymbolAddress(&hy_ptr,  g_hy);
    cudaGetSymbolAddress(&bar_ptr, g_bar);

    cudaMemsetAsync(hy_ptr, 0, sizeof(float)*NROW);
    cudaMemsetAsync(bar_ptr, 0, sizeof(unsigned));

    cudaFuncSetAttribute(step_kernel,
                         cudaFuncAttributeMaxDynamicSharedMemorySize, DSMEM_BYTES);

    bin_kernel<<<dim3(TT, MM), BIN_THR>>>(x, mask, W_in, bias);
    step_kernel<<<NB, NTHR, DSMEM_BYTES>>>(wm, conn, W_rec, out);
}

// round 10
// speedup vs baseline: 1.5880x; 1.5880x over previous
#include <cuda_runtime.h>

#define TT 256
#define MM 16
#define HH 256
#define II 128
#define NROW (MM*HH)          // 4096
#define NB 128                // 128 CTAs; 16 warps each; warp owns 2 rows of its module
#define NTHR 512
#define BIN_THR 256
#define KMAX 5                // wm slices cached in SMEM per row
#define SLOT (KMAX+1)         // +1 slot for wrec
#define WS_F4 (16*SLOT*128)   // per-CTA dynamic smem in float4 units = 192 KB
#define DSMEM_BYTES (WS_F4*16)

#define DT_ 0.042f
#define GAMMA_ 2.7f
#define EPS_ 4.7f

// ---- persistent scratch (no cudaMalloc allowed) ----
__device__ float    g_B[TT*NROW];     // W_in@u + bias, 4 MB
__device__ float    g_hy[2][NROW];    // double-buffered published hy
__device__ unsigned g_bar;

// ============================================================
// Precompute B[t, m*H+h]
// ============================================================
__global__ void bin_kernel(const float* __restrict__ x,
                           const float* __restrict__ input_mask,
                           const float* __restrict__ W_in,
                           const float* __restrict__ bias) {
    __shared__ float4 xs[II/4];
    int t = blockIdx.x, m = blockIdx.y, h = threadIdx.x;
    if (h < II/4) xs[h] = ((const float4*)(x + (size_t)t*II))[h];
    __syncthreads();
    const float4* w4 = (const float4*)(W_in + ((size_t)m*HH + h)*II);
    float s = 0.f;
#pragma unroll
    for (int k = 0; k < II/4; ++k) {
        float4 a = w4[k], b = xs[k];
        s += a.x*b.x + a.y*b.y + a.z*b.z + a.w*b.w;
    }
    g_B[((size_t)t*MM + m)*HH + h] = input_mask[m]*s + bias[m*HH + h];
}

__device__ __forceinline__ float dotf4(float4 a, float4 b) {
    return a.x*b.x + a.y*b.y + a.z*b.z + a.w*b.w;
}

// ============================================================
// Persistent step kernel. Warp w owns module i=w, rows
// h0=blockIdx.x and h1=128+blockIdx.x (balanced across CTAs).
// hy block is read from smem ONCE per warp and shared by both rows.
// Weights: KMAX blocks (x2 rows) + wrec in SMEM; rest stream from L2.
// ============================================================
__global__ void __launch_bounds__(NTHR, 1)
step_kernel(const float* __restrict__ wm,
            const float* __restrict__ conn,
            const float* __restrict__ wrec,
            float* __restrict__ out) {
    extern __shared__ float4 ws4[];      // [16 warps][SLOT][2 rows][64 f4] = 192 KB
    __shared__ float hy_sh[NROW];        // 16 KB snapshot
    __shared__ int   list_sh[MM][MM];
    __shared__ int   cnt_sh[MM];
    __shared__ float scal_sh[MM];

    int tid  = threadIdx.x;
    int lane = tid & 31;
    int i    = tid >> 5;                 // warp = module, 0..15
    int h0   = blockIdx.x;               // row A
    int h1   = 128 + blockIdx.x;         // row B
    int wsbase = i * SLOT * 128;         // float4 units

    if (tid < MM) {
        int c = 0; float s = 0.f;
#pragma unroll
        for (int o = 0; o < MM; ++o) {
            float v = conn[tid*MM + o];
            s += v;
            if (v != 0.f) list_sh[tid][c++] = o;
        }
        cnt_sh[tid]  = c;
        scal_sh[tid] = 1.f / fmaxf(s, 1.f);
    }
    __syncthreads();

    const int   cnt  = cnt_sh[i];
    const int   KC   = cnt < KMAX ? cnt : KMAX;
    const float scal = scal_sh[i];
    const float* wmb0 = wm + (((size_t)i*MM)*HH + h0)*HH;   // wm[i][o=0][h0][:]
    const float* wmb1 = wm + (((size_t)i*MM)*HH + h1)*HH;

    // ---- one-time weight preload into SMEM (both rows) ----
    for (int k = 0; k < KC; ++k) {
        int o = list_sh[i][k];
        const float4* s0 = (const float4*)(wmb0 + (size_t)o*HH*HH);
        const float4* s1 = (const float4*)(wmb1 + (size_t)o*HH*HH);
        ws4[wsbase + k*128 +       lane] = s0[lane];
        ws4[wsbase + k*128 + 32  + lane] = s0[lane+32];
        ws4[wsbase + k*128 + 64  + lane] = s1[lane];
        ws4[wsbase + k*128 + 96  + lane] = s1[lane+32];
    }
    {
        const float4* r0 = (const float4*)(wrec + ((size_t)i*HH + h0)*HH);
        const float4* r1 = (const float4*)(wrec + ((size_t)i*HH + h1)*HH);
        ws4[wsbase + KMAX*128 +      lane] = r0[lane];
        ws4[wsbase + KMAX*128 + 32 + lane] = r0[lane+32];
        ws4[wsbase + KMAX*128 + 64 + lane] = r1[lane];
        ws4[wsbase + KMAX*128 + 96 + lane] = r1[lane+32];
    }

    // register-resident state for both rows (kept redundantly in all lanes)
    float hypA = 0.f, hzpA = 0.f, hypB = 0.f, hzpB = 0.f;
    float BvA = g_B[i*HH + h0];
    float BvB = g_B[i*HH + h1];

    float* state_out = out;                       // [T][M][2][H]
    float* fb_out    = out + (size_t)TT*MM*2*HH;  // [T][M][H]
    unsigned* barp = &g_bar;

    for (int t = 0; t < TT; ++t) {
        int p = t & 1;
        // cooperative snapshot of published hy (2 float4/thread)
        {
            const float4* src = (const float4*)g_hy[p];
            ((float4*)hy_sh)[tid]        = __ldcg(src + tid);
            ((float4*)hy_sh)[tid + NTHR] = __ldcg(src + tid + NTHR);
        }
        __syncthreads();

        const float4* hy4 = (const float4*)hy_sh;
        float fbA0 = 0.f, fbA1 = 0.f, fbB0 = 0.f, fbB1 = 0.f;

        // ---- uncached blocks: weights from L2 (issued first), hy from smem ----
        for (int k = KC; k < cnt; ++k) {
            int o = list_sh[i][k];
            const float4* w0 = (const float4*)(wmb0 + (size_t)o*HH*HH);
            const float4* w1 = (const float4*)(wmb1 + (size_t)o*HH*HH);
            float4 a0 = w0[lane], a1 = w0[lane+32];
            float4 a2 = w1[lane], a3 = w1[lane+32];
            float4 b0 = hy4[o*64 + lane], b1 = hy4[o*64 + 32 + lane];
            fbA0 += dotf4(a0, b0) + dotf4(a1, b1);
            fbB0 += dotf4(a2, b0) + dotf4(a3, b1);
        }
        // ---- cached blocks: weights from smem, hy from smem (shared) ----
        for (int kk = 0; kk < KC; ++kk) {
            int o = list_sh[i][kk];
            float4 b0 = hy4[o*64 + lane], b1 = hy4[o*64 + 32 + lane];
            float4 a0 = ws4[wsbase + kk*128 +      lane];
            float4 a1 = ws4[wsbase + kk*128 + 32 + lane];
            float4 a2 = ws4[wsbase + kk*128 + 64 + lane];
            float4 a3 = ws4[wsbase + kk*128 + 96 + lane];
            fbA1 += dotf4(a0, b0) + dotf4(a1, b1);
            fbB1 += dotf4(a2, b0) + dotf4(a3, b1);
        }
        // ---- wrec (smem) ----
        float recA, recB;
        {
            float4 b0 = hy4[i*64 + lane], b1 = hy4[i*64 + 32 + lane];
            float4 a0 = ws4[wsbase + KMAX*128 +      lane];
            float4 a1 = ws4[wsbase + KMAX*128 + 32 + lane];
            float4 a2 = ws4[wsbase + KMAX*128 + 64 + lane];
            float4 a3 = ws4[wsbase + KMAX*128 + 96 + lane];
            recA = dotf4(a0, b0) + dotf4(a1, b1);
            recB = dotf4(a2, b0) + dotf4(a3, b1);
        }

        float fbA = fbA0 + fbA1, fbB = fbB0 + fbB1;
#pragma unroll
        for (int off = 16; off; off >>= 1) {
            fbA  += __shfl_xor_sync(0xffffffffu, fbA,  off);
            fbB  += __shfl_xor_sync(0xffffffffu, fbB,  off);
            recA += __shfl_xor_sync(0xffffffffu, recA, off);
            recB += __shfl_xor_sync(0xffffffffu, recB, off);
        }
        fbA *= scal; fbB *= scal;
        float preA = fbA + recA + BvA;
        float preB = fbB + recB + BvB;
        float hznA = hzpA + DT_ * (tanhf(preA) - GAMMA_*hypA - EPS_*hzpA);
        float hynA = hypA + DT_ * hznA;
        float hznB = hzpB + DT_ * (tanhf(preB) - GAMMA_*hypB - EPS_*hzpB);
        float hynB = hypB + DT_ * hznB;
        hzpA = hznA; hypA = hynA; hzpB = hznB; hypB = hynB;

        size_t sb = ((size_t)(t*MM + i)*2)*HH;
        if (lane == 0) {
            state_out[sb + h0]      = hynA;
            state_out[sb + HH + h0] = hznA;
            fb_out[(size_t)(t*MM + i)*HH + h0] = fbA;
            __stcg(&g_hy[1-p][i*HH + h0], hynA);
        } else if (lane == 1) {
            state_out[sb + h1]      = hynB;
            state_out[sb + HH + h1] = hznB;
            fb_out[(size_t)(t*MM + i)*HH + h1] = fbB;
            __stcg(&g_hy[1-p][i*HH + h1], hynB);
        }

        if (t == TT-1) break;

        // prefetch next-step B while the barrier drains
        BvA = g_B[(size_t)(t+1)*NROW + i*HH + h0];
        BvB = g_B[(size_t)(t+1)*NROW + i*HH + h1];

        __syncthreads();                 // all rows of CTA published
        if (tid == 0) {
            asm volatile("red.release.gpu.global.add.u32 [%0], 1;"
                         :: "l"(barp) : "memory");
            unsigned target = (unsigned)NB * (unsigned)(t + 1);
            unsigned v;
            do {
                asm volatile("ld.acquire.gpu.global.u32 %0, [%1];"
                             : "=r"(v) : "l"(barp) : "memory");
            } while (v < target);
        }
        __syncthreads();
    }
}

extern "C" void kernel_launch(void* const* d_in, const int* in_sizes, int n_in,
                              void* d_out, int out_size) {
    const float* x     = (const float*)d_in[0];
    const float* wm    = (const float*)d_in[1];
    const float* conn  = (const float*)d_in[2];
    const float* mask  = (const float*)d_in[3];
    const float* W_in  = (const float*)d_in[4];
    const float* W_rec = (const float*)d_in[5];
    const float* bias  = (const float*)d_in[6];
    float* out = (float*)d_out;

    void *hy_ptr, *bar_ptr;
    cudaGetSymbolAddress(&hy_ptr,  g_hy);
    cudaGetSymbolAddress(&bar_ptr, g_bar);

    cudaMemsetAsync(hy_ptr, 0, sizeof(float)*NROW);
    cudaMemsetAsync(bar_ptr, 0, sizeof(unsigned));

    cudaFuncSetAttribute(step_kernel,
                         cudaFuncAttributeMaxDynamicSharedMemorySize, DSMEM_BYTES);

    bin_kernel<<<dim3(TT, MM), BIN_THR>>>(x, mask, W_in, bias);
    step_kernel<<<NB, NTHR, DSMEM_BYTES>>>(wm, conn, W_rec, out);
}